// round 2
// baseline (speedup 1.0000x reference)
#include <cuda_runtime.h>
#include <math.h>

#define BB   16
#define NN   4096
#define KK   4096
#define NCHUNK 4
#define CHUNK  1024      // NN / NCHUNK
#define IN1  16384       // KK + 3*KK
#define H1   1024
#define H2   512
#define OUTD 256

// ---- scratch (no allocations allowed) ----
__device__ float g_best[BB * KK * NCHUNK];          // 1 MB
__device__ int   g_bidx[BB * KK * NCHUNK];          // 1 MB
__device__ float g_part1[64 * BB * H1];             // 4 MB
__device__ float g_h1[BB * H1];
__device__ float g_part2[16 * BB * H2];
__device__ float g_h2[BB * H2];
__device__ float g_part3[16 * BB * OUTD];

// ============================================================
// Kernel 1: partial argmin over an N-chunk, bit-matching the
// reference fp32 arithmetic:
//   pn    = rn(rn(x*x)+rn(y*y))+rn(z*z)         (mul + reduce-add)
//   cross = fma(b2,p2, fma(b1,p1, rn(b0*p0)))   (sgemm K=3 fma chain)
//   d2    = rn((bn+pn) - 2*cross)               (2*cross exact)
// grid: (KK/256, NCHUNK, BB), block: 256
// ============================================================
__global__ void k_argmin(const float* __restrict__ pc,
                         const float* __restrict__ basis) {
    __shared__ float4 sp[CHUNK];
    const int b  = blockIdx.z;
    const int c  = blockIdx.y;
    const int n0 = c * CHUNK;

    const float* pcb = pc + ((size_t)b * NN + n0) * 3;
    for (int n = threadIdx.x; n < CHUNK; n += blockDim.x) {
        float x = pcb[n * 3 + 0];
        float y = pcb[n * 3 + 1];
        float z = pcb[n * 3 + 2];
        float pn = __fadd_rn(__fadd_rn(__fmul_rn(x, x), __fmul_rn(y, y)),
                             __fmul_rn(z, z));
        sp[n] = make_float4(x, y, z, pn);
    }
    __syncthreads();

    const int k = blockIdx.x * blockDim.x + threadIdx.x;
    const float bx = basis[k * 3 + 0];
    const float by = basis[k * 3 + 1];
    const float bz = basis[k * 3 + 2];
    const float bn = __fadd_rn(__fadd_rn(__fmul_rn(bx, bx), __fmul_rn(by, by)),
                               __fmul_rn(bz, bz));

    float best = 3.0e38f;
    int   bi   = 0;
    #pragma unroll 8
    for (int n = 0; n < CHUNK; n++) {
        float4 p = sp[n];
        float cr = __fmaf_rn(bz, p.z, __fmaf_rn(by, p.y, __fmul_rn(bx, p.x)));
        float t  = __fadd_rn(bn, p.w);
        float d  = __fmaf_rn(-2.0f, cr, t);
        if (d < best) { best = d; bi = n; }   // strict < => first occurrence
    }

    const int o = (b * KK + k) * NCHUNK + c;
    g_best[o] = best;
    g_bidx[o] = n0 + bi;
}

// ============================================================
// Kernel 2: combine chunk partials (ascending chunk order, strict <,
// matching jnp.argmin first-occurrence), gather nearest point, write
// bps_feature row: [dists(4096) | deltas(4096*3)]
// ============================================================
__global__ void k_finish(const float* __restrict__ pc,
                         const float* __restrict__ basis,
                         float* __restrict__ out_bps) {
    const int t = blockIdx.x * blockDim.x + threadIdx.x;   // over BB*KK
    if (t >= BB * KK) return;
    const int b = t >> 12;          // /KK
    const int k = t & (KK - 1);

    float best = g_best[t * NCHUNK];
    int   bi   = g_bidx[t * NCHUNK];
    #pragma unroll
    for (int c = 1; c < NCHUNK; c++) {
        float v = g_best[t * NCHUNK + c];
        int   i = g_bidx[t * NCHUNK + c];
        if (v < best) { best = v; bi = i; }
    }

    const float* p = pc + ((size_t)b * NN + bi) * 3;
    const float dx = __fadd_rn(p[0], -basis[k * 3 + 0]);
    const float dy = __fadd_rn(p[1], -basis[k * 3 + 1]);
    const float dz = __fadd_rn(p[2], -basis[k * 3 + 2]);
    // norm: squares rounded, sequential adds, sqrt (matches reduce order)
    const float ss = __fadd_rn(__fadd_rn(__fmul_rn(dx, dx), __fmul_rn(dy, dy)),
                               __fmul_rn(dz, dz));
    const float dist = sqrtf(ss);

    float* row = out_bps + (size_t)b * IN1;
    row[k]              = dist;
    row[KK + 3 * k + 0] = dx;
    row[KK + 3 * k + 1] = dy;
    row[KK + 3 * k + 2] = dz;
}

// ============================================================
// Split-K GEMM: part[ic][m][j] = sum_{i in chunk ic} A[m][i] * W[i][j]
// A: [16][INsz], W: [INsz][H] row-major. 256 threads = 256 output cols.
// grid: (H/256, INsz/CI)
// ============================================================
template <int CI>
__global__ void k_gemm(const float* __restrict__ A,
                       const float* __restrict__ W,
                       float* __restrict__ part,
                       int INsz, int H) {
    __shared__ __align__(16) float sA[CI * 16];
    const int i0 = blockIdx.y * CI;

    for (int idx = threadIdx.x; idx < CI * 16; idx += 256) {
        const int m  = idx / CI;
        const int il = idx % CI;
        sA[il * 16 + m] = A[(size_t)m * INsz + i0 + il];
    }
    __syncthreads();

    const int j = blockIdx.x * 256 + threadIdx.x;
    float acc[16];
    #pragma unroll
    for (int m = 0; m < 16; m++) acc[m] = 0.0f;

    const float* wp = W + (size_t)i0 * H + j;
    #pragma unroll 4
    for (int il = 0; il < CI; il++) {
        const float w = *wp;
        wp += H;
        const float4* ap = (const float4*)(sA + il * 16);
        const float4 a0 = ap[0], a1 = ap[1], a2 = ap[2], a3 = ap[3];
        acc[0]  = fmaf(a0.x, w, acc[0]);
        acc[1]  = fmaf(a0.y, w, acc[1]);
        acc[2]  = fmaf(a0.z, w, acc[2]);
        acc[3]  = fmaf(a0.w, w, acc[3]);
        acc[4]  = fmaf(a1.x, w, acc[4]);
        acc[5]  = fmaf(a1.y, w, acc[5]);
        acc[6]  = fmaf(a1.z, w, acc[6]);
        acc[7]  = fmaf(a1.w, w, acc[7]);
        acc[8]  = fmaf(a2.x, w, acc[8]);
        acc[9]  = fmaf(a2.y, w, acc[9]);
        acc[10] = fmaf(a2.z, w, acc[10]);
        acc[11] = fmaf(a2.w, w, acc[11]);
        acc[12] = fmaf(a3.x, w, acc[12]);
        acc[13] = fmaf(a3.y, w, acc[13]);
        acc[14] = fmaf(a3.z, w, acc[14]);
        acc[15] = fmaf(a3.w, w, acc[15]);
    }

    float* pp = part + ((size_t)blockIdx.y * 16) * H + j;
    #pragma unroll
    for (int m = 0; m < 16; m++) pp[(size_t)m * H] = acc[m];
}

// ============================================================
// Deterministic split-K reduce + bias (+ optional leaky relu)
// ============================================================
__global__ void k_reduce(const float* __restrict__ part,
                         const float* __restrict__ bias,
                         float* __restrict__ outv,
                         int H, int nparts, int do_lrelu) {
    const int t = blockIdx.x * blockDim.x + threadIdx.x;
    const int total = BB * H;
    if (t >= total) return;
    float s = 0.0f;
    for (int p = 0; p < nparts; p++) s += part[(size_t)p * total + t];
    s += bias[t & (H - 1)];
    if (do_lrelu && s < 0.0f) s *= 0.2f;
    outv[t] = s;
}

// ============================================================
extern "C" void kernel_launch(void* const* d_in, const int* in_sizes, int n_in,
                              void* d_out, int out_size) {
    const float* pc    = (const float*)d_in[0];
    const float* basis = (const float*)d_in[1];
    const float* W1    = (const float*)d_in[2];
    const float* b1    = (const float*)d_in[3];
    const float* W2    = (const float*)d_in[4];
    const float* b2    = (const float*)d_in[5];
    const float* W3    = (const float*)d_in[6];
    const float* b3    = (const float*)d_in[7];

    float* out = (float*)d_out;            // global_feature: [16][256]
    float* bps = out + BB * OUTD;          // bps_feature:    [16][16384]

    float *p1, *p2, *p3, *h1, *h2;
    cudaGetSymbolAddress((void**)&p1, g_part1);
    cudaGetSymbolAddress((void**)&p2, g_part2);
    cudaGetSymbolAddress((void**)&p3, g_part3);
    cudaGetSymbolAddress((void**)&h1, g_h1);
    cudaGetSymbolAddress((void**)&h2, g_h2);

    k_argmin<<<dim3(KK / 256, NCHUNK, BB), 256>>>(pc, basis);
    k_finish<<<(BB * KK) / 256, 256>>>(pc, basis, bps);

    k_gemm<256><<<dim3(H1 / 256, IN1 / 256), 256>>>(bps, W1, p1, IN1, H1);
    k_reduce<<<(BB * H1) / 256, 256>>>(p1, b1, h1, H1, 64, 1);

    k_gemm<64><<<dim3(H2 / 256, H1 / 64), 256>>>(h1, W2, p2, H1, H2);
    k_reduce<<<(BB * H2) / 256, 256>>>(p2, b2, h2, H2, 16, 1);

    k_gemm<32><<<dim3(OUTD / 256, H2 / 32), 256>>>(h2, W3, p3, H2, OUTD);
    k_reduce<<<(BB * OUTD) / 256, 256>>>(p3, b3, out, OUTD, 16, 0);
}